// round 11
// baseline (speedup 1.0000x reference)
#include <cuda_runtime.h>
#include <math.h>
#include <stdint.h>

#define D   256
#define KC  100
#define BNEPS 1e-5f

// ------------------------- device scratch -------------------------
__device__ float  g_h1[32768 * 256];
__device__ float  g_p1[32768 * 256];
__device__ int    g_idx[32768];
__device__ float  g_stats[1024];
__device__ float  g_scale[512], g_shift[512];
__device__ float  g_cnt[KC];
__device__ float  g_embsq[KC];
__device__ float  g_laU[KC * 6];
__device__ float  g_hU[KC * D];
__device__ float  g_outU[KC * D];
__device__ float  g_scaleU[D], g_shiftU[D];
__device__ float  g_bsum[32768];
__device__ float  g_bcnt[32768];
__device__ double g_acc[8];   // 0 vq_sse, 1 loss_p, 2 loss_c, 3 loss_i, 5 latt

// ------------------------- helpers -------------------------
__device__ __forceinline__ uint32_t f2tf(float f) {
    uint32_t u;
    asm("cvt.rna.tf32.f32 %0, %1;" : "=r"(u) : "f"(f));
    return u;
}

__device__ __forceinline__ void mma8(float4& d, const uint32_t* a, const uint32_t* b) {
    asm("mma.sync.aligned.m16n8k8.row.col.f32.tf32.tf32.f32 "
        "{%0,%1,%2,%3}, {%4,%5,%6,%7}, {%8,%9}, {%0,%1,%2,%3};"
        : "+f"(d.x), "+f"(d.y), "+f"(d.z), "+f"(d.w)
        : "r"(a[0]), "r"(a[1]), "r"(a[2]), "r"(a[3]), "r"(b[0]), "r"(b[1]));
}

__device__ __forceinline__ void blk_atomic(float v, float* sred, double* dst) {
    int lane = threadIdx.x & 31, w = threadIdx.x >> 5;
#pragma unroll
    for (int o = 16; o; o >>= 1) v += __shfl_down_sync(0xffffffffu, v, o);
    if (lane == 0) sred[w] = v;
    __syncthreads();
    if (threadIdx.x == 0) {
        float s = 0.f;
#pragma unroll
        for (int i = 0; i < 8; i++) s += sred[i];
        atomicAdd(dst, (double)s);
    }
    __syncthreads();
}

// ------------------------- init + per-code precompute (merged) -------------------------
__global__ void k_pre(const float* __restrict__ emb, const float* __restrict__ lw,
                      const float* __restrict__ lb) {
    int t = threadIdx.x;
    if (blockIdx.x < 128) {
        int i = blockIdx.x * 256 + t;
        g_bsum[i] = 0.f;
        g_bcnt[i] = 0.f;
        if (i < 1024) g_stats[i] = 0.f;
        if (i < KC)   g_cnt[i] = 0.f;
        if (i < 8)    g_acc[i] = 0.0;
        return;
    }
    __shared__ float red[256];
    int k = blockIdx.x - 128;
    float v = emb[k * D + t];
    red[t] = v * v;
    __syncthreads();
#pragma unroll
    for (int s = 128; s > 0; s >>= 1) {
        if (t < s) red[t] += red[t + s];
        __syncthreads();
    }
    if (t == 0) g_embsq[k] = red[0];
    __syncthreads();
#pragma unroll
    for (int j = 0; j < 6; j++) {
        red[t] = v * lw[t * 6 + j];
        __syncthreads();
#pragma unroll
        for (int s = 128; s > 0; s >>= 1) {
            if (t < s) red[t] += red[t + s];
            __syncthreads();
        }
        if (t == 0) g_laU[k * 6 + j] = red[0] + lb[j];
        __syncthreads();
    }
}

// ==========================================================================
// Unified VQ + atom-CE tf32 GEMM. blockIdx < 256: VQ on z2. else atom on zn.
// Fragment-major smem: A fragments load as LDS.128, B as LDS.64.
// A gmem chunk prefetched into registers to hide DRAM latency under MMAs.
// ==========================================================================
__global__ __launch_bounds__(256, 2)
void k_cgemm(const float* __restrict__ z2, const float* __restrict__ zn,
             const float* __restrict__ embB, const float* __restrict__ aW,
             const float* __restrict__ ab, const int* __restrict__ tgt,
             const int* __restrict__ bidx,
             const float* __restrict__ ls, const float* __restrict__ smean,
             const float* __restrict__ sstd) {
    __shared__ uint4 As4[8 * 4 * 32];    // [mtile][ktile][lane] 16KB
    __shared__ uint2 Bs2[16 * 4 * 32];   // [ntile][ktile][lane] 16KB
    __shared__ float rowsq[256];
    __shared__ float pm1[128 * 4];
    __shared__ float pm2[128 * 4];
    __shared__ float rr[128];
    __shared__ int   stgt[128];
    __shared__ float sred[8];

    const int tid = threadIdx.x;
    const int lane = tid & 31, w = tid >> 5;
    const int g = lane >> 2, tig = lane & 3;
    const int wMt = (w >> 2) * 4, wNt = (w & 3) * 4;
    const int wM = (w >> 2) * 64, wN = (w & 3) * 32;
    const int nw = w & 3;

    const bool vq = (blockIdx.x < 256);
    const int m0 = (vq ? blockIdx.x : (blockIdx.x - 256)) * 128;
    const float* A = vq ? z2 : zn;

    if (!vq && tid < 128) stgt[tid] = tgt[m0 + tid];

    float4 acc[4][4];
#pragma unroll
    for (int i = 0; i < 4; i++)
#pragma unroll
        for (int j = 0; j < 4; j++) acc[i][j] = make_float4(0.f, 0.f, 0.f, 0.f);
    float asq = 0.f;

    // A staging map: thread -> (row arow, k halves)
    const int arow = tid >> 1, ac0 = (tid & 1) * 16;
    const int mt = arow >> 4, rrw = arow & 15;
    const int laneB = (rrw & 7) * 4, wB = rrw >> 3;
    // B staging map (atom): brow = k, bc0 = n group
    const int brow = tid >> 3, bc0 = (tid & 7) * 16;
    const int ktB = brow >> 3, b3 = brow & 3, wordB = (brow & 7) >> 2;
    // B staging map (vq): nB = emb row
    const int nB = tid >> 1, ks0 = (tid & 1) * 16;

    uint32_t* as = (uint32_t*)As4;
    uint32_t* bs = (uint32_t*)Bs2;

    // prefetch chunk 0 A
    float4 pa[4];
    {
        const float* Ap = A + (size_t)(m0 + arow) * D + ac0;
#pragma unroll
        for (int q = 0; q < 4; q++) pa[q] = *(const float4*)(Ap + q * 4);
    }

    for (int c = 0; c < 8; c++) {
        const int k0 = c * 32;
        // ---- stage A from prefetched regs ----
#pragma unroll
        for (int q = 0; q < 4; q++) {
            float4 v = pa[q];
            if (vq) asq += v.x * v.x + v.y * v.y + v.z * v.z + v.w * v.w;
            int cc = ac0 + q * 4;
            int kt = cc >> 3;
            int word = wB + 2 * ((cc >> 2) & 1);
            int base = ((mt * 4 + kt) * 32 + laneB) * 4 + word;
            as[base + 0]  = f2tf(v.x);
            as[base + 4]  = f2tf(v.y);
            as[base + 8]  = f2tf(v.z);
            as[base + 12] = f2tf(v.w);
        }
        // ---- stage B ----
        if (vq) {
            const float* Bp = embB + (size_t)nB * D + k0 + ks0;
            int ntb = ((nB >> 3) * 4) * 32 * 2 + ((nB & 7) * 4) * 2;
#pragma unroll
            for (int q = 0; q < 4; q++) {
                float4 v = (nB < KC) ? *(const float4*)(Bp + q * 4)
                                     : make_float4(0.f, 0.f, 0.f, 0.f);
                int kk0 = ks0 + q * 4;
                int kt = kk0 >> 3;
                int word = (kk0 >> 2) & 1;
                int base = ntb + kt * 64 + word;
                bs[base + 0] = f2tf(v.x);
                bs[base + 2] = f2tf(v.y);
                bs[base + 4] = f2tf(v.z);
                bs[base + 6] = f2tf(v.w);
            }
        } else {
            const float* Bp = aW + (size_t)(k0 + brow) * KC;
#pragma unroll
            for (int q = 0; q < 4; q++) {
                int j0 = bc0 + q * 4;
                float4 v = (j0 < KC) ? *(const float4*)(Bp + j0)
                                     : make_float4(0.f, 0.f, 0.f, 0.f);
#pragma unroll
                for (int e = 0; e < 4; e++) {
                    int j = j0 + e;
                    float ve = (e == 0) ? v.x : (e == 1) ? v.y : (e == 2) ? v.z : v.w;
                    int idx = (((j >> 3) * 4 + ktB) * 32 + ((j & 7) * 4 + b3)) * 2 + wordB;
                    bs[idx] = f2tf(ve);
                }
            }
        }
        __syncthreads();
        // ---- prefetch next chunk A (hidden under MMAs) ----
        if (c < 7) {
            const float* Ap = A + (size_t)(m0 + arow) * D + (k0 + 32) + ac0;
#pragma unroll
            for (int q = 0; q < 4; q++) pa[q] = *(const float4*)(Ap + q * 4);
        }
        // ---- MMAs ----
#pragma unroll
        for (int kt = 0; kt < 4; kt++) {
            uint4 af[4];
            uint2 bf[4];
#pragma unroll
            for (int mf = 0; mf < 4; mf++)
                af[mf] = As4[((wMt + mf) * 4 + kt) * 32 + lane];
#pragma unroll
            for (int nf = 0; nf < 4; nf++)
                bf[nf] = Bs2[((wNt + nf) * 4 + kt) * 32 + lane];
#pragma unroll
            for (int mf = 0; mf < 4; mf++)
#pragma unroll
                for (int nf = 0; nf < 4; nf++)
                    mma8(acc[mf][nf], (const uint32_t*)&af[mf], (const uint32_t*)&bf[nf]);
        }
        __syncthreads();
    }

    if (vq) {
        rowsq[arow * 2 + (tid & 1)] = asq;
        float bm[4][2];
        int   ba[4][2];
#pragma unroll
        for (int mf = 0; mf < 4; mf++) { bm[mf][0] = 3.4e38f; bm[mf][1] = 3.4e38f; ba[mf][0] = 0; ba[mf][1] = 0; }
#pragma unroll
        for (int mf = 0; mf < 4; mf++)
#pragma unroll
            for (int nf = 0; nf < 4; nf++) {
                int col0 = wN + nf * 8 + 2 * tig, col1 = col0 + 1;
                float4 cc = acc[mf][nf];
                float e0 = (col0 < KC) ? g_embsq[col0] : 3.0e38f;
                float e1 = (col1 < KC) ? g_embsq[col1] : 3.0e38f;
                float d0 = e0 - 2.f * cc.x;
                float d1 = e1 - 2.f * cc.y;
                float d2 = e0 - 2.f * cc.z;
                float d3 = e1 - 2.f * cc.w;
                if (col0 >= KC) { d0 = 3.0e38f; d2 = 3.0e38f; }
                if (col1 >= KC) { d1 = 3.0e38f; d3 = 3.0e38f; }
                if (d0 < bm[mf][0]) { bm[mf][0] = d0; ba[mf][0] = col0; }
                if (d1 < bm[mf][0]) { bm[mf][0] = d1; ba[mf][0] = col1; }
                if (d2 < bm[mf][1]) { bm[mf][1] = d2; ba[mf][1] = col0; }
                if (d3 < bm[mf][1]) { bm[mf][1] = d3; ba[mf][1] = col1; }
            }
#pragma unroll
        for (int mf = 0; mf < 4; mf++)
#pragma unroll
            for (int h = 0; h < 2; h++) {
#pragma unroll
                for (int o = 1; o <= 2; o <<= 1) {
                    float ov = __shfl_xor_sync(0xffffffffu, bm[mf][h], o);
                    int   oa = __shfl_xor_sync(0xffffffffu, ba[mf][h], o);
                    if (ov < bm[mf][h]) { bm[mf][h] = ov; ba[mf][h] = oa; }
                }
            }
        if (tig == 0) {
#pragma unroll
            for (int mf = 0; mf < 4; mf++)
#pragma unroll
                for (int h = 0; h < 2; h++) {
                    int row = wM + mf * 16 + g + h * 8;
                    pm1[row * 4 + nw] = bm[mf][h];
                    pm2[row * 4 + nw] = __int_as_float(ba[mf][h]);
                }
        }
        __syncthreads();
        float myloc = 0.f, mylat = 0.f;
        if (tid < 128) {
            float best = 3.4e38f;
            int barg = 0;
#pragma unroll
            for (int q = 0; q < 4; q++) {
                float v = pm1[tid * 4 + q];
                if (v < best) { best = v; barg = __float_as_int(pm2[tid * 4 + q]); }
            }
            int grow = m0 + tid;
            g_idx[grow] = barg;
            atomicAdd(&g_cnt[barg], 1.f);
            myloc = best + rowsq[tid * 2] + rowsq[tid * 2 + 1];
            float lat = 0.f;
#pragma unroll
            for (int j = 0; j < 6; j++) {
                float tv = (ls[(size_t)grow * 6 + j] - smean[j]) / sstd[j];
                float dd = g_laU[barg * 6 + j] - tv;
                lat += dd * dd;
            }
            mylat = lat;
        }
        blk_atomic(myloc, sred, &g_acc[0]);
        blk_atomic(mylat, sred, &g_acc[5]);
    } else {
        float bb0[4], bb1[4];
#pragma unroll
        for (int nf = 0; nf < 4; nf++) {
            int col0 = wN + nf * 8 + 2 * tig, col1 = col0 + 1;
            bb0[nf] = (col0 < KC) ? __ldg(&ab[col0]) : 0.f;
            bb1[nf] = (col1 < KC) ? __ldg(&ab[col1]) : 0.f;
        }
        float mx[4][2];
#pragma unroll
        for (int mf = 0; mf < 4; mf++) { mx[mf][0] = -3.4e38f; mx[mf][1] = -3.4e38f; }
#pragma unroll
        for (int mf = 0; mf < 4; mf++)
#pragma unroll
            for (int nf = 0; nf < 4; nf++) {
                int col0 = wN + nf * 8 + 2 * tig, col1 = col0 + 1;
                float4 cc = acc[mf][nf];
                cc.x += bb0[nf]; cc.y += bb1[nf]; cc.z += bb0[nf]; cc.w += bb1[nf];
                acc[mf][nf] = cc;
                if (col0 < KC) { mx[mf][0] = fmaxf(mx[mf][0], cc.x); mx[mf][1] = fmaxf(mx[mf][1], cc.z); }
                if (col1 < KC) { mx[mf][0] = fmaxf(mx[mf][0], cc.y); mx[mf][1] = fmaxf(mx[mf][1], cc.w); }
            }
#pragma unroll
        for (int mf = 0; mf < 4; mf++)
#pragma unroll
            for (int h = 0; h < 2; h++) {
#pragma unroll
                for (int o = 1; o <= 2; o <<= 1)
                    mx[mf][h] = fmaxf(mx[mf][h], __shfl_xor_sync(0xffffffffu, mx[mf][h], o));
            }
        if (tig == 0) {
#pragma unroll
            for (int mf = 0; mf < 4; mf++)
#pragma unroll
                for (int h = 0; h < 2; h++) {
                    int row = wM + mf * 16 + g + h * 8;
                    pm1[row * 4 + nw] = mx[mf][h];
                }
        }
        __syncthreads();
        if (tid < 128) {
            rr[tid] = fmaxf(fmaxf(pm1[tid * 4 + 0], pm1[tid * 4 + 1]),
                            fmaxf(pm1[tid * 4 + 2], pm1[tid * 4 + 3]));
        }
        __syncthreads();
        float se[4][2], tl[4][2];
#pragma unroll
        for (int mf = 0; mf < 4; mf++) { se[mf][0] = 0.f; se[mf][1] = 0.f; tl[mf][0] = 0.f; tl[mf][1] = 0.f; }
#pragma unroll
        for (int mf = 0; mf < 4; mf++) {
            int r0 = wM + mf * 16 + g, r1 = r0 + 8;
            float m0v = rr[r0], m1v = rr[r1];
            int t0 = stgt[r0], t1 = stgt[r1];
#pragma unroll
            for (int nf = 0; nf < 4; nf++) {
                int col0 = wN + nf * 8 + 2 * tig, col1 = col0 + 1;
                float4 cc = acc[mf][nf];
                if (col0 < KC) {
                    se[mf][0] += __expf(cc.x - m0v);
                    se[mf][1] += __expf(cc.z - m1v);
                    if (col0 == t0) tl[mf][0] = cc.x;
                    if (col0 == t1) tl[mf][1] = cc.z;
                }
                if (col1 < KC) {
                    se[mf][0] += __expf(cc.y - m0v);
                    se[mf][1] += __expf(cc.w - m1v);
                    if (col1 == t0) tl[mf][0] = cc.y;
                    if (col1 == t1) tl[mf][1] = cc.w;
                }
            }
        }
#pragma unroll
        for (int mf = 0; mf < 4; mf++)
#pragma unroll
            for (int h = 0; h < 2; h++) {
#pragma unroll
                for (int o = 1; o <= 2; o <<= 1) {
                    se[mf][h] += __shfl_xor_sync(0xffffffffu, se[mf][h], o);
                    tl[mf][h] += __shfl_xor_sync(0xffffffffu, tl[mf][h], o);
                }
            }
        if (tig == 0) {
#pragma unroll
            for (int mf = 0; mf < 4; mf++)
#pragma unroll
                for (int h = 0; h < 2; h++) {
                    int row = wM + mf * 16 + g + h * 8;
                    pm1[row * 4 + nw] = se[mf][h];
                    pm2[row * 4 + nw] = tl[mf][h];
                }
        }
        __syncthreads();
        if (tid < 128) {
            float S = pm1[tid * 4] + pm1[tid * 4 + 1] + pm1[tid * 4 + 2] + pm1[tid * 4 + 3];
            float T = pm2[tid * 4] + pm2[tid * 4 + 1] + pm2[tid * 4 + 2] + pm2[tid * 4 + 3];
            float ce = rr[tid] + __logf(S) - T;
            int gb = bidx[m0 + tid];
            atomicAdd(&g_bsum[gb], ce);
            atomicAdd(&g_bcnt[gb], 1.f);
        }
    }
}

// ==========================================================================
// tf32 D x D MLP GEMM, fragment-major smem + A-register prefetch.
// EPI 0: store C + column sum/sumsq; EPI 1: store C + loss_p; EPI 2: loss_c only.
// ==========================================================================
template <int EPI, int BN>
__global__ __launch_bounds__(256, 2)
void k_dgemm(const float* __restrict__ Aext, int aSel,
             const float* __restrict__ Bw, const float* __restrict__ bias,
             int outSel, int bank, const float* __restrict__ cmp) {
    __shared__ uint4 As4[8 * 4 * 32];
    __shared__ uint2 Bs2[16 * 4 * 32];
    __shared__ float sS[256], sH[256];
    __shared__ int   sidx[128];
    __shared__ float sred[8];

    const int tid = threadIdx.x;
    const int lane = tid & 31, w = tid >> 5;
    const int g = lane >> 2, tig = lane & 3;
    const int wMt = (w >> 2) * 4, wNt = (w & 3) * 4;
    const int wM = (w >> 2) * 64, wN = (w & 3) * 32;
    const int m0 = blockIdx.y * 128, n0 = blockIdx.x * 128;

    const float* A = (aSel == 0) ? Aext : ((aSel == 1) ? g_h1 : g_p1);
    float* Cp = (outSel == 1) ? g_h1 : g_p1;

    if (BN) {
        sS[tid] = g_scale[bank * 256 + tid];
        sH[tid] = g_shift[bank * 256 + tid];
    }
    if (EPI == 1 && tid < 128) sidx[tid] = g_idx[m0 + tid];

    float4 acc[4][4];
#pragma unroll
    for (int i = 0; i < 4; i++)
#pragma unroll
        for (int j = 0; j < 4; j++) acc[i][j] = make_float4(0.f, 0.f, 0.f, 0.f);

    const int arow = tid >> 1, ac0 = (tid & 1) * 16;
    const int mt = arow >> 4, rrw = arow & 15;
    const int laneB = (rrw & 7) * 4, wB = rrw >> 3;
    const int brow = tid >> 3, bc0 = (tid & 7) * 16;
    const int ktB = brow >> 3, b3 = brow & 3, wordB = (brow & 7) >> 2;

    uint32_t* as = (uint32_t*)As4;
    uint32_t* bs = (uint32_t*)Bs2;

    if (BN) __syncthreads();   // sS/sH visible before staging uses them

    float4 pa[4];
    {
        const float* Ap = A + (size_t)(m0 + arow) * D + ac0;
#pragma unroll
        for (int q = 0; q < 4; q++) pa[q] = *(const float4*)(Ap + q * 4);
    }

    for (int c = 0; c < 8; c++) {
        const int k0 = c * 32;
#pragma unroll
        for (int q = 0; q < 4; q++) {
            float4 v = pa[q];
            int cc = ac0 + q * 4;
            if (BN) {
                int kc = k0 + cc;
                v.x = fmaxf(0.f, fmaf(v.x, sS[kc + 0], sH[kc + 0]));
                v.y = fmaxf(0.f, fmaf(v.y, sS[kc + 1], sH[kc + 1]));
                v.z = fmaxf(0.f, fmaf(v.z, sS[kc + 2], sH[kc + 2]));
                v.w = fmaxf(0.f, fmaf(v.w, sS[kc + 3], sH[kc + 3]));
            }
            int kt = cc >> 3;
            int word = wB + 2 * ((cc >> 2) & 1);
            int base = ((mt * 4 + kt) * 32 + laneB) * 4 + word;
            as[base + 0]  = f2tf(v.x);
            as[base + 4]  = f2tf(v.y);
            as[base + 8]  = f2tf(v.z);
            as[base + 12] = f2tf(v.w);
        }
        {
            const float* Bp = Bw + (size_t)(k0 + brow) * D + n0 + bc0;
#pragma unroll
            for (int q = 0; q < 4; q++) {
                float4 v = *(const float4*)(Bp + q * 4);
#pragma unroll
                for (int e = 0; e < 4; e++) {
                    int j = bc0 + q * 4 + e;
                    float ve = (e == 0) ? v.x : (e == 1) ? v.y : (e == 2) ? v.z : v.w;
                    int idx = (((j >> 3) * 4 + ktB) * 32 + ((j & 7) * 4 + b3)) * 2 + wordB;
                    bs[idx] = f2tf(ve);
                }
            }
        }
        __syncthreads();
        if (c < 7) {
            const float* Ap = A + (size_t)(m0 + arow) * D + (k0 + 32) + ac0;
#pragma unroll
            for (int q = 0; q < 4; q++) pa[q] = *(const float4*)(Ap + q * 4);
        }
#pragma unroll
        for (int kt = 0; kt < 4; kt++) {
            uint4 af[4];
            uint2 bf[4];
#pragma unroll
            for (int mf = 0; mf < 4; mf++)
                af[mf] = As4[((wMt + mf) * 4 + kt) * 32 + lane];
#pragma unroll
            for (int nf = 0; nf < 4; nf++)
                bf[nf] = Bs2[((wNt + nf) * 4 + kt) * 32 + lane];
#pragma unroll
            for (int mf = 0; mf < 4; mf++)
#pragma unroll
                for (int nf = 0; nf < 4; nf++)
                    mma8(acc[mf][nf], (const uint32_t*)&af[mf], (const uint32_t*)&bf[nf]);
        }
        __syncthreads();
    }

    float bb0[4], bb1[4];
#pragma unroll
    for (int nf = 0; nf < 4; nf++) {
        int col = n0 + wN + nf * 8 + 2 * tig;
        bb0[nf] = __ldg(&bias[col]);
        bb1[nf] = __ldg(&bias[col + 1]);
    }

    if (EPI == 0) {
        float ps[4][2], ps2[4][2];
#pragma unroll
        for (int nf = 0; nf < 4; nf++) { ps[nf][0] = ps[nf][1] = 0.f; ps2[nf][0] = ps2[nf][1] = 0.f; }
#pragma unroll
        for (int mf = 0; mf < 4; mf++) {
            int r0 = m0 + wM + mf * 16 + g, r1 = r0 + 8;
#pragma unroll
            for (int nf = 0; nf < 4; nf++) {
                int col = n0 + wN + nf * 8 + 2 * tig;
                float4 cc = acc[mf][nf];
                cc.x += bb0[nf]; cc.y += bb1[nf]; cc.z += bb0[nf]; cc.w += bb1[nf];
                *(float2*)(Cp + (size_t)r0 * D + col) = make_float2(cc.x, cc.y);
                *(float2*)(Cp + (size_t)r1 * D + col) = make_float2(cc.z, cc.w);
                ps[nf][0] += cc.x + cc.z;            ps[nf][1] += cc.y + cc.w;
                ps2[nf][0] += cc.x * cc.x + cc.z * cc.z;  ps2[nf][1] += cc.y * cc.y + cc.w * cc.w;
            }
        }
#pragma unroll
        for (int nf = 0; nf < 4; nf++)
#pragma unroll
            for (int b = 0; b < 2; b++) {
#pragma unroll
                for (int o = 16; o >= 4; o >>= 1) {
                    ps[nf][b] += __shfl_down_sync(0xffffffffu, ps[nf][b], o);
                    ps2[nf][b] += __shfl_down_sync(0xffffffffu, ps2[nf][b], o);
                }
            }
        if (g == 0) {
#pragma unroll
            for (int nf = 0; nf < 4; nf++)
#pragma unroll
                for (int b = 0; b < 2; b++) {
                    int col = n0 + wN + nf * 8 + 2 * tig + b;
                    atomicAdd(&g_stats[bank * 512 + col], ps[nf][b]);
                    atomicAdd(&g_stats[bank * 512 + 256 + col], ps2[nf][b]);
                }
        }
    } else if (EPI == 1) {
        float loc = 0.f;
#pragma unroll
        for (int mf = 0; mf < 4; mf++) {
            int rl0 = wM + mf * 16 + g, rl1 = rl0 + 8;
            int r0 = m0 + rl0, r1 = m0 + rl1;
            const float* e0 = cmp + (size_t)sidx[rl0] * D;
            const float* e1 = cmp + (size_t)sidx[rl1] * D;
#pragma unroll
            for (int nf = 0; nf < 4; nf++) {
                int col = n0 + wN + nf * 8 + 2 * tig;
                float4 cc = acc[mf][nf];
                cc.x += bb0[nf]; cc.y += bb1[nf]; cc.z += bb0[nf]; cc.w += bb1[nf];
                *(float2*)(Cp + (size_t)r0 * D + col) = make_float2(cc.x, cc.y);
                *(float2*)(Cp + (size_t)r1 * D + col) = make_float2(cc.z, cc.w);
                float2 v0 = __ldg((const float2*)(e0 + col));
                float2 v1 = __ldg((const float2*)(e1 + col));
                float d0 = cc.x - v0.x, d1 = cc.y - v0.y, d2 = cc.z - v1.x, d3 = cc.w - v1.y;
                loc += d0 * d0 + d1 * d1 + d2 * d2 + d3 * d3;
            }
        }
        blk_atomic(loc, sred, &g_acc[1]);
    } else {
        float loc = 0.f;
#pragma unroll
        for (int mf = 0; mf < 4; mf++) {
            int r0 = m0 + wM + mf * 16 + g, r1 = r0 + 8;
#pragma unroll
            for (int nf = 0; nf < 4; nf++) {
                int col = n0 + wN + nf * 8 + 2 * tig;
                float4 cc = acc[mf][nf];
                cc.x += bb0[nf]; cc.y += bb1[nf]; cc.z += bb0[nf]; cc.w += bb1[nf];
                float2 v0 = __ldg((const float2*)(cmp + (size_t)r0 * D + col));
                float2 v1 = __ldg((const float2*)(cmp + (size_t)r1 * D + col));
                float d0 = cc.x - v0.x, d1 = cc.y - v0.y, d2 = cc.z - v1.x, d3 = cc.w - v1.y;
                loc += d0 * d0 + d1 * d1 + d2 * d2 + d3 * d3;
            }
        }
        blk_atomic(loc, sred, &g_acc[2]);
    }
}

// ------------------------- BN stats -> combined scale/shift -------------------------
__global__ void k_stats(int bank, const float* __restrict__ g,
                        const float* __restrict__ beta, float invB) {
    int t = threadIdx.x;
    float s = g_stats[bank * 512 + t];
    float s2 = g_stats[bank * 512 + 256 + t];
    float mu = s * invB;
    float var = s2 * invB - mu * mu;
    float rs = rsqrtf(var + BNEPS);
    float sc = rs * g[t];
    g_scale[bank * 256 + t] = sc;
    g_shift[bank * 256 + t] = beta[t] - mu * sc;
}

// ------------------------- unique-code (loss_i) path -------------------------
__global__ void k_hU(const float* __restrict__ emb, const float* __restrict__ W1,
                     const float* __restrict__ b1) {
    __shared__ float e[256];
    int k = blockIdx.x, t = threadIdx.x;
    e[t] = emb[k * D + t];
    __syncthreads();
    float acc = 0.f;
#pragma unroll 4
    for (int d = 0; d < D; d++) acc = fmaf(e[d], W1[(size_t)d * D + t], acc);
    g_hU[k * D + t] = acc + b1[t];
}

__global__ void k_statsU(const float* __restrict__ g, const float* __restrict__ beta,
                         float invB) {
    int t = threadIdx.x;
    float s = 0.f, s2 = 0.f;
#pragma unroll 4
    for (int k = 0; k < KC; k++) {
        float c = g_cnt[k];
        float h = g_hU[k * D + t];
        s += c * h;
        s2 += c * h * h;
    }
    float mu = s * invB;
    float var = s2 * invB - mu * mu;
    float rs = rsqrtf(var + BNEPS);
    float sc = rs * g[t];
    g_scaleU[t] = sc;
    g_shiftU[t] = beta[t] - mu * sc;
}

__global__ void k_outU(const float* __restrict__ W2, const float* __restrict__ b2) {
    __shared__ float a[256];
    int k = blockIdx.x, t = threadIdx.x;
    a[t] = fmaxf(0.f, fmaf(g_hU[k * D + t], g_scaleU[t], g_shiftU[t]));
    __syncthreads();
    float acc = 0.f;
#pragma unroll 4
    for (int d = 0; d < D; d++) acc = fmaf(a[d], W2[(size_t)d * D + t], acc);
    g_outU[k * D + t] = acc + b2[t];
}

__global__ void k_lossi(const float* __restrict__ z1) {
    __shared__ float sred[8];
    int t = threadIdx.x;
    size_t base = (size_t)blockIdx.x * 2048;
    float loc = 0.f;
#pragma unroll
    for (int s = 0; s < 8; s++) {
        size_t i = base + (size_t)s * 256 + t;
        int row = (int)(i >> 8);
        int c = (int)(i & 255);
        float o = g_outU[g_idx[row] * D + c];
        float dd = z1[i] - o;
        loc += dd * dd;
    }
    blk_atomic(loc, sred, &g_acc[3]);
}

// ------------------------- final combine -------------------------
__global__ void k_final(float* __restrict__ out, int out_size, int B) {
    __shared__ double dred[1024];
    int t = threadIdx.x;
    double s = 0.0;
    for (int b = t; b < B; b += 1024)
        s += (double)g_bsum[b] / (double)fmaxf(g_bcnt[b], 1.0f);
    dred[t] = s;
    __syncthreads();
#pragma unroll
    for (int st = 512; st > 0; st >>= 1) {
        if (t < st) dred[t] += dred[t + st];
        __syncthreads();
    }
    if (t == 0) {
        double invBD = 1.0 / ((double)B * (double)D);
        double atom = dred[0] / (double)B;
        double vq = 2.0 * g_acc[0] * invBD;
        double lp = g_acc[1] * invBD;
        double lc = g_acc[2] * invBD;
        double li = g_acc[3] * invBD;
        double cyc = lp + li + lc;
        double latt = g_acc[5] / ((double)B * 6.0) * 10.0;
        double loss = cyc + atom + latt + vq;
        float vals[5] = {(float)loss, (float)cyc, (float)atom, (float)latt, (float)vq};
        for (int i = 0; i < out_size; i++) out[i] = (i < 5) ? vals[i] : 0.f;
    }
}

// ------------------------- launch -------------------------
extern "C" void kernel_launch(void* const* d_in, const int* in_sizes, int n_in,
                              void* d_out, int out_size) {
    const float* z1   = (const float*)d_in[0];
    const float* z2   = (const float*)d_in[1];
    const float* zn   = (const float*)d_in[2];
    const float* emb  = (const float*)d_in[3];
    const float* pW1  = (const float*)d_in[4];
    const float* pb1  = (const float*)d_in[5];
    const float* pg   = (const float*)d_in[6];
    const float* pbe  = (const float*)d_in[7];
    const float* pW2  = (const float*)d_in[8];
    const float* pb2  = (const float*)d_in[9];
    const float* iW1  = (const float*)d_in[10];
    const float* ib1  = (const float*)d_in[11];
    const float* ig   = (const float*)d_in[12];
    const float* ibe  = (const float*)d_in[13];
    const float* iW2  = (const float*)d_in[14];
    const float* ib2  = (const float*)d_in[15];
    const float* lw   = (const float*)d_in[16];
    const float* lb   = (const float*)d_in[17];
    const float* aW   = (const float*)d_in[18];
    const float* ab   = (const float*)d_in[19];
    const float* smean = (const float*)d_in[20];
    const float* sstd  = (const float*)d_in[21];
    const float* ls    = (const float*)d_in[22];
    const int* bidx = (const int*)d_in[24];
    const int* anum = (const int*)d_in[25];

    int B = in_sizes[0] / D;    // 32768
    int NA = in_sizes[2] / D;   // 262144
    float invB = 1.0f / (float)B;

    k_pre<<<228, 256>>>(emb, lw, lb);

    // unified: blocks [0,256) VQ on z2, [256, 256+NA/128) atom CE on zn
    k_cgemm<<<256 + NA / 128, 256>>>(z2, zn, emb, aW, ab, anum, bidx, ls, smean, sstd);

    dim3 gg(2, B / 128);
    k_dgemm<0, 0><<<gg, 256>>>(z1, 0, pW1, pb1, 1, 0, nullptr);
    k_stats<<<1, 256>>>(0, pg, pbe, invB);
    k_dgemm<1, 1><<<gg, 256>>>(nullptr, 1, pW2, pb2, 2, 0, emb);
    k_dgemm<0, 0><<<gg, 256>>>(nullptr, 2, iW1, ib1, 1, 1, nullptr);
    k_stats<<<1, 256>>>(1, ig, ibe, invB);
    k_dgemm<2, 1><<<gg, 256>>>(nullptr, 1, iW2, ib2, 0, 1, z1);

    k_hU<<<KC, 256>>>(emb, iW1, ib1);
    k_statsU<<<1, 256>>>(ig, ibe, invB);
    k_outU<<<KC, 256>>>(iW2, ib2);
    k_lossi<<<B / 8, 256>>>(z1);

    k_final<<<1, 1024>>>((float*)d_out, out_size, B);
}

// round 12
// speedup vs baseline: 1.7582x; 1.7582x over previous
#include <cuda_runtime.h>
#include <math.h>
#include <stdint.h>

#define D   256
#define KC  100
#define BNEPS 1e-5f
#define LDA 36
#define LDB 136

// ------------------------- device scratch -------------------------
__device__ float  g_h1[32768 * 256];
__device__ float  g_p1[32768 * 256];
__device__ int    g_idx[32768];
__device__ float  g_stats[1024];
__device__ float  g_scale[512], g_shift[512];
__device__ float  g_cnt[KC];
__device__ float  g_embsq[KC];
__device__ float  g_laU[KC * 6];
__device__ float  g_hU[KC * D];
__device__ float  g_outU[KC * D];
__device__ float  g_scaleU[D], g_shiftU[D];
__device__ float  g_bsum[32768];
__device__ float  g_bcnt[32768];
__device__ double g_acc[8];   // 0 vq_sse, 1 loss_p, 2 loss_c, 3 loss_i, 5 latt

// ------------------------- helpers -------------------------
__device__ __forceinline__ uint32_t f2tf(float f) {
    uint32_t u;
    asm("cvt.rna.tf32.f32 %0, %1;" : "=r"(u) : "f"(f));
    return u;
}

__device__ __forceinline__ void mma8(float4& d, const uint32_t* a, const uint32_t* b) {
    asm("mma.sync.aligned.m16n8k8.row.col.f32.tf32.tf32.f32 "
        "{%0,%1,%2,%3}, {%4,%5,%6,%7}, {%8,%9}, {%0,%1,%2,%3};"
        : "+f"(d.x), "+f"(d.y), "+f"(d.z), "+f"(d.w)
        : "r"(a[0]), "r"(a[1]), "r"(a[2]), "r"(a[3]), "r"(b[0]), "r"(b[1]));
}

__device__ __forceinline__ void blk_atomic(float v, float* sred, double* dst) {
    int lane = threadIdx.x & 31, w = threadIdx.x >> 5;
#pragma unroll
    for (int o = 16; o; o >>= 1) v += __shfl_down_sync(0xffffffffu, v, o);
    if (lane == 0) sred[w] = v;
    __syncthreads();
    if (threadIdx.x == 0) {
        float s = 0.f;
#pragma unroll
        for (int i = 0; i < 8; i++) s += sred[i];
        atomicAdd(dst, (double)s);
    }
    __syncthreads();
}

// ------------------------- init + per-code precompute (merged) -------------------------
__global__ void k_pre(const float* __restrict__ emb, const float* __restrict__ lw,
                      const float* __restrict__ lb) {
    int t = threadIdx.x;
    if (blockIdx.x < 128) {
        int i = blockIdx.x * 256 + t;
        g_bsum[i] = 0.f;
        g_bcnt[i] = 0.f;
        if (i < 1024) g_stats[i] = 0.f;
        if (i < KC)   g_cnt[i] = 0.f;
        if (i < 8)    g_acc[i] = 0.0;
        return;
    }
    __shared__ float red[256];
    int k = blockIdx.x - 128;
    float v = emb[k * D + t];
    red[t] = v * v;
    __syncthreads();
#pragma unroll
    for (int s = 128; s > 0; s >>= 1) {
        if (t < s) red[t] += red[t + s];
        __syncthreads();
    }
    if (t == 0) g_embsq[k] = red[0];
    __syncthreads();
#pragma unroll
    for (int j = 0; j < 6; j++) {
        red[t] = v * lw[t * 6 + j];
        __syncthreads();
#pragma unroll
        for (int s = 128; s > 0; s >>= 1) {
            if (t < s) red[t] += red[t + s];
            __syncthreads();
        }
        if (t == 0) g_laU[k * 6 + j] = red[0] + lb[j];
        __syncthreads();
    }
}

// ==========================================================================
// Unified VQ + atom-CE tf32 GEMM. blockIdx < 256: VQ on z2, else atom on zn.
// ROUND-5 smem layout (measured good): scalar staging, LDA=36 / LDB=136.
// NEW: A gmem chunk prefetched into registers; merged VQ+atom grid.
// ==========================================================================
__global__ __launch_bounds__(256, 2)
void k_cgemm(const float* __restrict__ z2, const float* __restrict__ zn,
             const float* __restrict__ embB, const float* __restrict__ aW,
             const float* __restrict__ ab, const int* __restrict__ tgt,
             const int* __restrict__ bidx,
             const float* __restrict__ ls, const float* __restrict__ smean,
             const float* __restrict__ sstd) {
    __shared__ uint32_t As[128 * LDA];
    __shared__ uint32_t Bs[32 * LDB];
    __shared__ float rowsq[256];
    __shared__ float pm1[128 * 4];
    __shared__ float pm2[128 * 4];
    __shared__ float rr[128];
    __shared__ int   stgt[128];
    __shared__ float sred[8];

    const int tid = threadIdx.x;
    const int lane = tid & 31, w = tid >> 5;
    const int g = lane >> 2, tig = lane & 3;
    const int wM = (w >> 2) * 64, wN = (w & 3) * 32;
    const int nw = w & 3;

    const bool vq = (blockIdx.x < 256);
    const int m0 = (vq ? blockIdx.x : (blockIdx.x - 256)) * 128;
    const float* A = vq ? z2 : zn;

    if (!vq && tid < 128) stgt[tid] = tgt[m0 + tid];

    float4 acc[4][4];
#pragma unroll
    for (int i = 0; i < 4; i++)
#pragma unroll
        for (int j = 0; j < 4; j++) acc[i][j] = make_float4(0.f, 0.f, 0.f, 0.f);
    float asq = 0.f;

    const int arow = tid >> 1, ac0 = (tid & 1) * 16;
    const int brow = tid >> 3, bc0 = (tid & 7) * 16;   // atom B map
    const int nB = tid >> 1, ks0 = (tid & 1) * 16;     // vq B map

    // prefetch chunk 0 of A
    float4 pa[4];
    {
        const float* Ap = A + (size_t)(m0 + arow) * D + ac0;
#pragma unroll
        for (int q = 0; q < 4; q++) pa[q] = *(const float4*)(Ap + q * 4);
    }

    for (int c = 0; c < 8; c++) {
        const int k0 = c * 32;
        __syncthreads();
        // ---- stage A from prefetched regs ----
#pragma unroll
        for (int q = 0; q < 4; q++) {
            float4 v = pa[q];
            if (vq) asq += v.x * v.x + v.y * v.y + v.z * v.z + v.w * v.w;
            int cc = ac0 + q * 4;
            As[arow * LDA + cc + 0] = f2tf(v.x);
            As[arow * LDA + cc + 1] = f2tf(v.y);
            As[arow * LDA + cc + 2] = f2tf(v.z);
            As[arow * LDA + cc + 3] = f2tf(v.w);
        }
        // ---- stage B ----
        if (vq) {
#pragma unroll
            for (int e = 0; e < 16; e++) {
                int kk = ks0 + e;
                float v = (nB < KC) ? embB[(size_t)nB * D + k0 + kk] : 0.f;
                Bs[kk * LDB + nB] = f2tf(v);
            }
        } else {
#pragma unroll
            for (int e = 0; e < 16; e++) {
                int n = bc0 + e;
                float v = (n < KC) ? aW[(size_t)(k0 + brow) * KC + n] : 0.f;
                Bs[brow * LDB + n] = f2tf(v);
            }
        }
        __syncthreads();
        // ---- prefetch next chunk A (overlapped with MMAs) ----
        if (c < 7) {
            const float* Ap = A + (size_t)(m0 + arow) * D + (k0 + 32) + ac0;
#pragma unroll
            for (int q = 0; q < 4; q++) pa[q] = *(const float4*)(Ap + q * 4);
        }
        // ---- MMAs ----
#pragma unroll
        for (int ks = 0; ks < 4; ks++) {
            const int kb = ks * 8;
            uint32_t af[4][4];
#pragma unroll
            for (int mf = 0; mf < 4; mf++) {
                int mb = wM + mf * 16;
                af[mf][0] = As[(mb + g) * LDA + kb + tig];
                af[mf][1] = As[(mb + g + 8) * LDA + kb + tig];
                af[mf][2] = As[(mb + g) * LDA + kb + tig + 4];
                af[mf][3] = As[(mb + g + 8) * LDA + kb + tig + 4];
            }
            uint32_t bf[4][2];
#pragma unroll
            for (int nf = 0; nf < 4; nf++) {
                int n = wN + nf * 8 + g;
                bf[nf][0] = Bs[(kb + tig) * LDB + n];
                bf[nf][1] = Bs[(kb + tig + 4) * LDB + n];
            }
#pragma unroll
            for (int mf = 0; mf < 4; mf++)
#pragma unroll
                for (int nf = 0; nf < 4; nf++)
                    mma8(acc[mf][nf], af[mf], bf[nf]);
        }
    }
    __syncthreads();

    if (vq) {
        rowsq[arow * 2 + (tid & 1)] = asq;
        float bm[4][2];
        int   ba[4][2];
#pragma unroll
        for (int mf = 0; mf < 4; mf++) { bm[mf][0] = 3.4e38f; bm[mf][1] = 3.4e38f; ba[mf][0] = 0; ba[mf][1] = 0; }
#pragma unroll
        for (int mf = 0; mf < 4; mf++)
#pragma unroll
            for (int nf = 0; nf < 4; nf++) {
                int col0 = wN + nf * 8 + 2 * tig, col1 = col0 + 1;
                float4 cc = acc[mf][nf];
                float e0 = (col0 < KC) ? g_embsq[col0] : 3.0e38f;
                float e1 = (col1 < KC) ? g_embsq[col1] : 3.0e38f;
                float d0 = e0 - 2.f * cc.x;
                float d1 = e1 - 2.f * cc.y;
                float d2 = e0 - 2.f * cc.z;
                float d3 = e1 - 2.f * cc.w;
                if (col0 >= KC) { d0 = 3.0e38f; d2 = 3.0e38f; }
                if (col1 >= KC) { d1 = 3.0e38f; d3 = 3.0e38f; }
                if (d0 < bm[mf][0]) { bm[mf][0] = d0; ba[mf][0] = col0; }
                if (d1 < bm[mf][0]) { bm[mf][0] = d1; ba[mf][0] = col1; }
                if (d2 < bm[mf][1]) { bm[mf][1] = d2; ba[mf][1] = col0; }
                if (d3 < bm[mf][1]) { bm[mf][1] = d3; ba[mf][1] = col1; }
            }
#pragma unroll
        for (int mf = 0; mf < 4; mf++)
#pragma unroll
            for (int h = 0; h < 2; h++) {
#pragma unroll
                for (int o = 1; o <= 2; o <<= 1) {
                    float ov = __shfl_xor_sync(0xffffffffu, bm[mf][h], o);
                    int   oa = __shfl_xor_sync(0xffffffffu, ba[mf][h], o);
                    if (ov < bm[mf][h]) { bm[mf][h] = ov; ba[mf][h] = oa; }
                }
            }
        if (tig == 0) {
#pragma unroll
            for (int mf = 0; mf < 4; mf++)
#pragma unroll
                for (int h = 0; h < 2; h++) {
                    int row = wM + mf * 16 + g + h * 8;
                    pm1[row * 4 + nw] = bm[mf][h];
                    pm2[row * 4 + nw] = __int_as_float(ba[mf][h]);
                }
        }
        __syncthreads();
        float myloc = 0.f, mylat = 0.f;
        if (tid < 128) {
            float best = 3.4e38f;
            int barg = 0;
#pragma unroll
            for (int q = 0; q < 4; q++) {
                float v = pm1[tid * 4 + q];
                if (v < best) { best = v; barg = __float_as_int(pm2[tid * 4 + q]); }
            }
            int grow = m0 + tid;
            g_idx[grow] = barg;
            atomicAdd(&g_cnt[barg], 1.f);
            myloc = best + rowsq[tid * 2] + rowsq[tid * 2 + 1];
            float lat = 0.f;
#pragma unroll
            for (int j = 0; j < 6; j++) {
                float tv = (ls[(size_t)grow * 6 + j] - smean[j]) / sstd[j];
                float dd = g_laU[barg * 6 + j] - tv;
                lat += dd * dd;
            }
            mylat = lat;
        }
        blk_atomic(myloc, sred, &g_acc[0]);
        blk_atomic(mylat, sred, &g_acc[5]);
    } else {
        float bb0[4], bb1[4];
#pragma unroll
        for (int nf = 0; nf < 4; nf++) {
            int col0 = wN + nf * 8 + 2 * tig, col1 = col0 + 1;
            bb0[nf] = (col0 < KC) ? __ldg(&ab[col0]) : 0.f;
            bb1[nf] = (col1 < KC) ? __ldg(&ab[col1]) : 0.f;
        }
        float mx[4][2];
#pragma unroll
        for (int mf = 0; mf < 4; mf++) { mx[mf][0] = -3.4e38f; mx[mf][1] = -3.4e38f; }
#pragma unroll
        for (int mf = 0; mf < 4; mf++)
#pragma unroll
            for (int nf = 0; nf < 4; nf++) {
                int col0 = wN + nf * 8 + 2 * tig, col1 = col0 + 1;
                float4 cc = acc[mf][nf];
                cc.x += bb0[nf]; cc.y += bb1[nf]; cc.z += bb0[nf]; cc.w += bb1[nf];
                acc[mf][nf] = cc;
                if (col0 < KC) { mx[mf][0] = fmaxf(mx[mf][0], cc.x); mx[mf][1] = fmaxf(mx[mf][1], cc.z); }
                if (col1 < KC) { mx[mf][0] = fmaxf(mx[mf][0], cc.y); mx[mf][1] = fmaxf(mx[mf][1], cc.w); }
            }
#pragma unroll
        for (int mf = 0; mf < 4; mf++)
#pragma unroll
            for (int h = 0; h < 2; h++) {
#pragma unroll
                for (int o = 1; o <= 2; o <<= 1)
                    mx[mf][h] = fmaxf(mx[mf][h], __shfl_xor_sync(0xffffffffu, mx[mf][h], o));
            }
        if (tig == 0) {
#pragma unroll
            for (int mf = 0; mf < 4; mf++)
#pragma unroll
                for (int h = 0; h < 2; h++) {
                    int row = wM + mf * 16 + g + h * 8;
                    pm1[row * 4 + nw] = mx[mf][h];
                }
        }
        __syncthreads();
        if (tid < 128) {
            rr[tid] = fmaxf(fmaxf(pm1[tid * 4 + 0], pm1[tid * 4 + 1]),
                            fmaxf(pm1[tid * 4 + 2], pm1[tid * 4 + 3]));
        }
        __syncthreads();
        float se[4][2], tl[4][2];
#pragma unroll
        for (int mf = 0; mf < 4; mf++) { se[mf][0] = 0.f; se[mf][1] = 0.f; tl[mf][0] = 0.f; tl[mf][1] = 0.f; }
#pragma unroll
        for (int mf = 0; mf < 4; mf++) {
            int r0 = wM + mf * 16 + g, r1 = r0 + 8;
            float m0v = rr[r0], m1v = rr[r1];
            int t0 = stgt[r0], t1 = stgt[r1];
#pragma unroll
            for (int nf = 0; nf < 4; nf++) {
                int col0 = wN + nf * 8 + 2 * tig, col1 = col0 + 1;
                float4 cc = acc[mf][nf];
                if (col0 < KC) {
                    se[mf][0] += __expf(cc.x - m0v);
                    se[mf][1] += __expf(cc.z - m1v);
                    if (col0 == t0) tl[mf][0] = cc.x;
                    if (col0 == t1) tl[mf][1] = cc.z;
                }
                if (col1 < KC) {
                    se[mf][0] += __expf(cc.y - m0v);
                    se[mf][1] += __expf(cc.w - m1v);
                    if (col1 == t0) tl[mf][0] = cc.y;
                    if (col1 == t1) tl[mf][1] = cc.w;
                }
            }
        }
#pragma unroll
        for (int mf = 0; mf < 4; mf++)
#pragma unroll
            for (int h = 0; h < 2; h++) {
#pragma unroll
                for (int o = 1; o <= 2; o <<= 1) {
                    se[mf][h] += __shfl_xor_sync(0xffffffffu, se[mf][h], o);
                    tl[mf][h] += __shfl_xor_sync(0xffffffffu, tl[mf][h], o);
                }
            }
        if (tig == 0) {
#pragma unroll
            for (int mf = 0; mf < 4; mf++)
#pragma unroll
                for (int h = 0; h < 2; h++) {
                    int row = wM + mf * 16 + g + h * 8;
                    pm1[row * 4 + nw] = se[mf][h];
                    pm2[row * 4 + nw] = tl[mf][h];
                }
        }
        __syncthreads();
        if (tid < 128) {
            float S = pm1[tid * 4] + pm1[tid * 4 + 1] + pm1[tid * 4 + 2] + pm1[tid * 4 + 3];
            float T = pm2[tid * 4] + pm2[tid * 4 + 1] + pm2[tid * 4 + 2] + pm2[tid * 4 + 3];
            float ce = rr[tid] + __logf(S) - T;
            int gb = bidx[m0 + tid];
            atomicAdd(&g_bsum[gb], ce);
            atomicAdd(&g_bcnt[gb], 1.f);
        }
    }
}

// ==========================================================================
// tf32 D x D MLP GEMM — Round-5 layout + A-register prefetch.
// EPI 0: store C + column sum/sumsq; EPI 1: store C + loss_p; EPI 2: loss_c only.
// ==========================================================================
template <int EPI, int BN>
__global__ __launch_bounds__(256, 2)
void k_dgemm(const float* __restrict__ Aext, int aSel,
             const float* __restrict__ Bw, const float* __restrict__ bias,
             int outSel, int bank, const float* __restrict__ cmp) {
    __shared__ uint32_t As[128 * LDA];
    __shared__ uint32_t Bs[32 * LDB];
    __shared__ float sS[256], sH[256];
    __shared__ int   sidx[128];
    __shared__ float sred[8];

    const int tid = threadIdx.x;
    const int lane = tid & 31, w = tid >> 5;
    const int g = lane >> 2, tig = lane & 3;
    const int wM = (w >> 2) * 64, wN = (w & 3) * 32;
    const int m0 = blockIdx.y * 128, n0 = blockIdx.x * 128;

    const float* A = (aSel == 0) ? Aext : ((aSel == 1) ? g_h1 : g_p1);
    float* Cp = (outSel == 1) ? g_h1 : g_p1;

    if (BN) {
        sS[tid] = g_scale[bank * 256 + tid];
        sH[tid] = g_shift[bank * 256 + tid];
    }
    if (EPI == 1 && tid < 128) sidx[tid] = g_idx[m0 + tid];

    float4 acc[4][4];
#pragma unroll
    for (int i = 0; i < 4; i++)
#pragma unroll
        for (int j = 0; j < 4; j++) acc[i][j] = make_float4(0.f, 0.f, 0.f, 0.f);

    const int arow = tid >> 1, ac0 = (tid & 1) * 16;
    const int brow = tid >> 3, bc0 = (tid & 7) * 16;

    float4 pa[4];
    {
        const float* Ap = A + (size_t)(m0 + arow) * D + ac0;
#pragma unroll
        for (int q = 0; q < 4; q++) pa[q] = *(const float4*)(Ap + q * 4);
    }

    for (int c = 0; c < 8; c++) {
        const int k0 = c * 32;
        __syncthreads();
        // stage A (BN applied from smem constants)
#pragma unroll
        for (int q = 0; q < 4; q++) {
            float4 v = pa[q];
            int cc = ac0 + q * 4;
            if (BN) {
                int kc = k0 + cc;
                v.x = fmaxf(0.f, fmaf(v.x, sS[kc + 0], sH[kc + 0]));
                v.y = fmaxf(0.f, fmaf(v.y, sS[kc + 1], sH[kc + 1]));
                v.z = fmaxf(0.f, fmaf(v.z, sS[kc + 2], sH[kc + 2]));
                v.w = fmaxf(0.f, fmaf(v.w, sS[kc + 3], sH[kc + 3]));
            }
            As[arow * LDA + cc + 0] = f2tf(v.x);
            As[arow * LDA + cc + 1] = f2tf(v.y);
            As[arow * LDA + cc + 2] = f2tf(v.z);
            As[arow * LDA + cc + 3] = f2tf(v.w);
        }
        // stage B
        {
            const float* Bp = Bw + (size_t)(k0 + brow) * D + n0 + bc0;
#pragma unroll
            for (int q = 0; q < 4; q++) {
                float4 v = *(const float4*)(Bp + q * 4);
                int cc = bc0 + q * 4;
                Bs[brow * LDB + cc + 0] = f2tf(v.x);
                Bs[brow * LDB + cc + 1] = f2tf(v.y);
                Bs[brow * LDB + cc + 2] = f2tf(v.z);
                Bs[brow * LDB + cc + 3] = f2tf(v.w);
            }
        }
        __syncthreads();
        if (c < 7) {
            const float* Ap = A + (size_t)(m0 + arow) * D + (k0 + 32) + ac0;
#pragma unroll
            for (int q = 0; q < 4; q++) pa[q] = *(const float4*)(Ap + q * 4);
        }
#pragma unroll
        for (int ks = 0; ks < 4; ks++) {
            const int kb = ks * 8;
            uint32_t af[4][4];
#pragma unroll
            for (int mf = 0; mf < 4; mf++) {
                int mb = wM + mf * 16;
                af[mf][0] = As[(mb + g) * LDA + kb + tig];
                af[mf][1] = As[(mb + g + 8) * LDA + kb + tig];
                af[mf][2] = As[(mb + g) * LDA + kb + tig + 4];
                af[mf][3] = As[(mb + g + 8) * LDA + kb + tig + 4];
            }
            uint32_t bf[4][2];
#pragma unroll
            for (int nf = 0; nf < 4; nf++) {
                int n = wN + nf * 8 + g;
                bf[nf][0] = Bs[(kb + tig) * LDB + n];
                bf[nf][1] = Bs[(kb + tig + 4) * LDB + n];
            }
#pragma unroll
            for (int mf = 0; mf < 4; mf++)
#pragma unroll
                for (int nf = 0; nf < 4; nf++)
                    mma8(acc[mf][nf], af[mf], bf[nf]);
        }
    }
    __syncthreads();

    float bb0[4], bb1[4];
#pragma unroll
    for (int nf = 0; nf < 4; nf++) {
        int col = n0 + wN + nf * 8 + 2 * tig;
        bb0[nf] = __ldg(&bias[col]);
        bb1[nf] = __ldg(&bias[col + 1]);
    }

    if (EPI == 0) {
        float ps[4][2], ps2[4][2];
#pragma unroll
        for (int nf = 0; nf < 4; nf++) { ps[nf][0] = ps[nf][1] = 0.f; ps2[nf][0] = ps2[nf][1] = 0.f; }
#pragma unroll
        for (int mf = 0; mf < 4; mf++) {
            int r0 = m0 + wM + mf * 16 + g, r1 = r0 + 8;
#pragma unroll
            for (int nf = 0; nf < 4; nf++) {
                int col = n0 + wN + nf * 8 + 2 * tig;
                float4 cc = acc[mf][nf];
                cc.x += bb0[nf]; cc.y += bb1[nf]; cc.z += bb0[nf]; cc.w += bb1[nf];
                *(float2*)(Cp + (size_t)r0 * D + col) = make_float2(cc.x, cc.y);
                *(float2*)(Cp + (size_t)r1 * D + col) = make_float2(cc.z, cc.w);
                ps[nf][0] += cc.x + cc.z;            ps[nf][1] += cc.y + cc.w;
                ps2[nf][0] += cc.x * cc.x + cc.z * cc.z;  ps2[nf][1] += cc.y * cc.y + cc.w * cc.w;
            }
        }
#pragma unroll
        for (int nf = 0; nf < 4; nf++)
#pragma unroll
            for (int b = 0; b < 2; b++) {
#pragma unroll
                for (int o = 16; o >= 4; o >>= 1) {
                    ps[nf][b] += __shfl_down_sync(0xffffffffu, ps[nf][b], o);
                    ps2[nf][b] += __shfl_down_sync(0xffffffffu, ps2[nf][b], o);
                }
            }
        if (g == 0) {
#pragma unroll
            for (int nf = 0; nf < 4; nf++)
#pragma unroll
                for (int b = 0; b < 2; b++) {
                    int col = n0 + wN + nf * 8 + 2 * tig + b;
                    atomicAdd(&g_stats[bank * 512 + col], ps[nf][b]);
                    atomicAdd(&g_stats[bank * 512 + 256 + col], ps2[nf][b]);
                }
        }
    } else if (EPI == 1) {
        float loc = 0.f;
#pragma unroll
        for (int mf = 0; mf < 4; mf++) {
            int rl0 = wM + mf * 16 + g, rl1 = rl0 + 8;
            int r0 = m0 + rl0, r1 = m0 + rl1;
            const float* e0 = cmp + (size_t)sidx[rl0] * D;
            const float* e1 = cmp + (size_t)sidx[rl1] * D;
#pragma unroll
            for (int nf = 0; nf < 4; nf++) {
                int col = n0 + wN + nf * 8 + 2 * tig;
                float4 cc = acc[mf][nf];
                cc.x += bb0[nf]; cc.y += bb1[nf]; cc.z += bb0[nf]; cc.w += bb1[nf];
                *(float2*)(Cp + (size_t)r0 * D + col) = make_float2(cc.x, cc.y);
                *(float2*)(Cp + (size_t)r1 * D + col) = make_float2(cc.z, cc.w);
                float2 v0 = __ldg((const float2*)(e0 + col));
                float2 v1 = __ldg((const float2*)(e1 + col));
                float d0 = cc.x - v0.x, d1 = cc.y - v0.y, d2 = cc.z - v1.x, d3 = cc.w - v1.y;
                loc += d0 * d0 + d1 * d1 + d2 * d2 + d3 * d3;
            }
        }
        blk_atomic(loc, sred, &g_acc[1]);
    } else {
        float loc = 0.f;
#pragma unroll
        for (int mf = 0; mf < 4; mf++) {
            int r0 = m0 + wM + mf * 16 + g, r1 = r0 + 8;
#pragma unroll
            for (int nf = 0; nf < 4; nf++) {
                int col = n0 + wN + nf * 8 + 2 * tig;
                float4 cc = acc[mf][nf];
                cc.x += bb0[nf]; cc.y += bb1[nf]; cc.z += bb0[nf]; cc.w += bb1[nf];
                float2 v0 = __ldg((const float2*)(cmp + (size_t)r0 * D + col));
                float2 v1 = __ldg((const float2*)(cmp + (size_t)r1 * D + col));
                float d0 = cc.x - v0.x, d1 = cc.y - v0.y, d2 = cc.z - v1.x, d3 = cc.w - v1.y;
                loc += d0 * d0 + d1 * d1 + d2 * d2 + d3 * d3;
            }
        }
        blk_atomic(loc, sred, &g_acc[2]);
    }
}

// ------------------------- BN stats -> combined scale/shift -------------------------
__global__ void k_stats(int bank, const float* __restrict__ g,
                        const float* __restrict__ beta, float invB) {
    int t = threadIdx.x;
    float s = g_stats[bank * 512 + t];
    float s2 = g_stats[bank * 512 + 256 + t];
    float mu = s * invB;
    float var = s2 * invB - mu * mu;
    float rs = rsqrtf(var + BNEPS);
    float sc = rs * g[t];
    g_scale[bank * 256 + t] = sc;
    g_shift[bank * 256 + t] = beta[t] - mu * sc;
}

// ------------------------- unique-code (loss_i) path -------------------------
__global__ void k_hU(const float* __restrict__ emb, const float* __restrict__ W1,
                     const float* __restrict__ b1) {
    __shared__ float e[256];
    int k = blockIdx.x, t = threadIdx.x;
    e[t] = emb[k * D + t];
    __syncthreads();
    float acc = 0.f;
#pragma unroll 4
    for (int d = 0; d < D; d++) acc = fmaf(e[d], W1[(size_t)d * D + t], acc);
    g_hU[k * D + t] = acc + b1[t];
}

__global__ void k_statsU(const float* __restrict__ g, const float* __restrict__ beta,
                         float invB) {
    int t = threadIdx.x;
    float s = 0.f, s2 = 0.f;
#pragma unroll 4
    for (int k = 0; k < KC; k++) {
        float c = g_cnt[k];
        float h = g_hU[k * D + t];
        s += c * h;
        s2 += c * h * h;
    }
    float mu = s * invB;
    float var = s2 * invB - mu * mu;
    float rs = rsqrtf(var + BNEPS);
    float sc = rs * g[t];
    g_scaleU[t] = sc;
    g_shiftU[t] = beta[t] - mu * sc;
}

__global__ void k_outU(const float* __restrict__ W2, const float* __restrict__ b2) {
    __shared__ float a[256];
    int k = blockIdx.x, t = threadIdx.x;
    a[t] = fmaxf(0.f, fmaf(g_hU[k * D + t], g_scaleU[t], g_shiftU[t]));
    __syncthreads();
    float acc = 0.f;
#pragma unroll 4
    for (int d = 0; d < D; d++) acc = fmaf(a[d], W2[(size_t)d * D + t], acc);
    g_outU[k * D + t] = acc + b2[t];
}

__global__ void k_lossi(const float* __restrict__ z1) {
    __shared__ float sred[8];
    int t = threadIdx.x;
    size_t base = (size_t)blockIdx.x * 2048;
    float loc = 0.f;
#pragma unroll
    for (int s = 0; s < 8; s++) {
        size_t i = base + (size_t)s * 256 + t;
        int row = (int)(i >> 8);
        int c = (int)(i & 255);
        float o = g_outU[g_idx[row] * D + c];
        float dd = z1[i] - o;
        loc += dd * dd;
    }
    blk_atomic(loc, sred, &g_acc[3]);
}

// ------------------------- final combine -------------------------
__global__ void k_final(float* __restrict__ out, int out_size, int B) {
    __shared__ double dred[1024];
    int t = threadIdx.x;
    double s = 0.0;
    for (int b = t; b < B; b += 1024)
        s += (double)g_bsum[b] / (double)fmaxf(g_bcnt[b], 1.0f);
    dred[t] = s;
    __syncthreads();
#pragma unroll
    for (int st = 512; st > 0; st >>= 1) {
        if (t < st) dred[t] += dred[t + st];
        __syncthreads();
    }
    if (t == 0) {
        double invBD = 1.0 / ((double)B * (double)D);
        double atom = dred[0] / (double)B;
        double vq = 2.0 * g_acc[0] * invBD;
        double lp = g_acc[1] * invBD;
        double lc = g_acc[2] * invBD;
        double li = g_acc[3] * invBD;
        double cyc = lp + li + lc;
        double latt = g_acc[5] / ((double)B * 6.0) * 10.0;
        double loss = cyc + atom + latt + vq;
        float vals[5] = {(float)loss, (float)cyc, (float)atom, (float)latt, (float)vq};
        for (int i = 0; i < out_size; i++) out[i] = (i < 5) ? vals[i] : 0.f;
    }
}

// ------------------------- launch -------------------------
extern "C" void kernel_launch(void* const* d_in, const int* in_sizes, int n_in,
                              void* d_out, int out_size) {
    const float* z1   = (const float*)d_in[0];
    const float* z2   = (const float*)d_in[1];
    const float* zn   = (const float*)d_in[2];
    const float* emb  = (const float*)d_in[3];
    const float* pW1  = (const float*)d_in[4];
    const float* pb1  = (const float*)d_in[5];
    const float* pg   = (const float*)d_in[6];
    const float* pbe  = (const float*)d_in[7];
    const float* pW2  = (const float*)d_in[8];
    const float* pb2  = (const float*)d_in[9];
    const float* iW1  = (const float*)d_in[10];
    const float* ib1  = (const float*)d_in[11];
    const float* ig   = (const float*)d_in[12];
    const float* ibe  = (const float*)d_in[13];
    const float* iW2  = (const float*)d_in[14];
    const float* ib2  = (const float*)d_in[15];
    const float* lw   = (const float*)d_in[16];
    const float* lb   = (const float*)d_in[17];
    const float* aW   = (const float*)d_in[18];
    const float* ab   = (const float*)d_in[19];
    const float* smean = (const float*)d_in[20];
    const float* sstd  = (const float*)d_in[21];
    const float* ls    = (const float*)d_in[22];
    const int* bidx = (const int*)d_in[24];
    const int* anum = (const int*)d_in[25];

    int B = in_sizes[0] / D;    // 32768
    int NA = in_sizes[2] / D;   // 262144
    float invB = 1.0f / (float)B;

    k_pre<<<228, 256>>>(emb, lw, lb);

    // unified: blocks [0,256) VQ on z2, [256, 256+NA/128) atom CE on zn
    k_cgemm<<<256 + NA / 128, 256>>>(z2, zn, emb, aW, ab, anum, bidx, ls, smean, sstd);

    dim3 gg(2, B / 128);
    k_dgemm<0, 0><<<gg, 256>>>(z1, 0, pW1, pb1, 1, 0, nullptr);
    k_stats<<<1, 256>>>(0, pg, pbe, invB);
    k_dgemm<1, 1><<<gg, 256>>>(nullptr, 1, pW2, pb2, 2, 0, emb);
    k_dgemm<0, 0><<<gg, 256>>>(nullptr, 2, iW1, ib1, 1, 1, nullptr);
    k_stats<<<1, 256>>>(1, ig, ibe, invB);
    k_dgemm<2, 1><<<gg, 256>>>(nullptr, 1, iW2, ib2, 0, 1, z1);

    k_hU<<<KC, 256>>>(emb, iW1, ib1);
    k_statsU<<<1, 256>>>(ig, ibe, invB);
    k_outU<<<KC, 256>>>(iW2, ib2);
    k_lossi<<<B / 8, 256>>>(z1);

    k_final<<<1, 1024>>>((float*)d_out, out_size, B);
}